// round 1
// baseline (speedup 1.0000x reference)
#include <cuda_runtime.h>
#include <cstdint>

// NegativeLogLikelihood (Cox partial likelihood) for N=16.7M time-sorted samples.
// cost = -( sum_i ev_i * (pred_i - log(cumsum_i exp(pred))) ) / sum_i ev_i
//
// Single-pass decoupled-lookback scan over exp(pred), fused with the
// event-masked reduction. Reads pred (fp32) + yevent (int32) exactly once
// (~128 MiB); ytime is unused by the math and never touched. Output: 1 float.

#define BLOCK      256
#define ITEMS      16
#define TILE       (BLOCK * ITEMS)      // 4096 elements per block
#define MAX_BLOCKS 8192                 // N=16777216 -> 4096 blocks

#define FLAG_INV 0u
#define FLAG_AGG 1u
#define FLAG_INC 2u

// Scratch (no allocation allowed): descriptors + global accumulators.
__device__ unsigned long long g_desc[MAX_BLOCKS];
__device__ double             g_sum;
__device__ int                g_cnt;

__device__ __forceinline__ unsigned long long ld_desc(const unsigned long long* p) {
    unsigned long long v;
    asm volatile("ld.volatile.global.u64 %0, [%1];" : "=l"(v) : "l"(p));
    return v;
}
__device__ __forceinline__ void st_desc(unsigned long long* p, unsigned long long v) {
    asm volatile("st.global.release.gpu.u64 [%0], %1;" :: "l"(p), "l"(v) : "memory");
}
__device__ __forceinline__ unsigned long long pack_desc(unsigned flag, float v) {
    return ((unsigned long long)flag << 32) | (unsigned long long)__float_as_uint(v);
}
__device__ __forceinline__ float desc_val(unsigned long long d) {
    return __uint_as_float((unsigned)(d & 0xffffffffu));
}
__device__ __forceinline__ unsigned desc_flag(unsigned long long d) {
    return (unsigned)(d >> 32);
}

__global__ void nll_reset_kernel(int nblocks) {
    int i = blockIdx.x * blockDim.x + threadIdx.x;
    if (i < nblocks) g_desc[i] = 0ull;
    if (i == 0) { g_sum = 0.0; g_cnt = 0; }
}

__global__ void __launch_bounds__(BLOCK)
nll_scan_kernel(const float* __restrict__ pred,
                const int*   __restrict__ yevent,
                int n) {
    __shared__ float s_warp[BLOCK / 32];
    __shared__ float s_prefix;
    __shared__ float s_loc[BLOCK / 32];
    __shared__ int   s_cnt[BLOCK / 32];

    const int bid  = blockIdx.x;
    const int tid  = threadIdx.x;
    const int lane = tid & 31;
    const int wid  = tid >> 5;

    const long long base = (long long)bid * TILE + (long long)tid * ITEMS;
    const bool full = (base + ITEMS) <= (long long)n;

    // ---- load pred + local sequential inclusive cumsum of exp(pred) ----
    float p[ITEMS];
    float c[ITEMS];
    if (full) {
        const float4* p4 = reinterpret_cast<const float4*>(pred + base);
#pragma unroll
        for (int j = 0; j < ITEMS / 4; j++) {
            float4 v = p4[j];
            p[j * 4 + 0] = v.x; p[j * 4 + 1] = v.y;
            p[j * 4 + 2] = v.z; p[j * 4 + 3] = v.w;
        }
        float run = 0.f;
#pragma unroll
        for (int k = 0; k < ITEMS; k++) { run += __expf(p[k]); c[k] = run; }
    } else {
        float run = 0.f;
#pragma unroll
        for (int k = 0; k < ITEMS; k++) {
            bool inb = (base + k) < (long long)n;
            p[k] = inb ? pred[base + k] : 0.f;
            run += inb ? __expf(p[k]) : 0.f;
            c[k] = run;
        }
    }
    const float thread_total = c[ITEMS - 1];

    // ---- block-wide exclusive scan of per-thread totals ----
    float x = thread_total;
#pragma unroll
    for (int d = 1; d < 32; d <<= 1) {
        float y = __shfl_up_sync(0xffffffffu, x, d);
        if (lane >= d) x += y;
    }
    if (lane == 31) s_warp[wid] = x;
    __syncthreads();
    if (wid == 0) {
        float w = (lane < BLOCK / 32) ? s_warp[lane] : 0.f;
#pragma unroll
        for (int d = 1; d < BLOCK / 32; d <<= 1) {
            float y = __shfl_up_sync(0xffffffffu, w, d);
            if (lane >= d) w += y;
        }
        if (lane < BLOCK / 32) s_warp[lane] = w;
    }
    __syncthreads();
    const float warp_excl   = (wid > 0) ? s_warp[wid - 1] : 0.f;
    const float thread_excl = warp_excl + (x - thread_total);
    const float block_total = s_warp[BLOCK / 32 - 1];

    // ---- decoupled lookback (warp 0) ----
    if (wid == 0) {
        if (lane == 0) {
            unsigned long long v = (bid == 0) ? pack_desc(FLAG_INC, block_total)
                                              : pack_desc(FLAG_AGG, block_total);
            st_desc(&g_desc[bid], v);
        }
        float excl_prefix = 0.f;
        if (bid > 0) {
            int window_hi = bid - 1;
            while (true) {
                int idx = window_hi - lane;
                unsigned long long d;
                unsigned f;
                do {
                    d = (idx >= 0) ? ld_desc(&g_desc[idx]) : pack_desc(FLAG_INC, 0.f);
                    f = desc_flag(d);
                } while (__any_sync(0xffffffffu, f == FLAG_INV));
                float val = desc_val(d);
                unsigned incmask = __ballot_sync(0xffffffffu, f == FLAG_INC);
                if (incmask) {
                    int first = __ffs(incmask) - 1;   // nearest predecessor w/ inclusive
                    float contrib = (lane <= first) ? val : 0.f;
#pragma unroll
                    for (int s = 16; s; s >>= 1)
                        contrib += __shfl_xor_sync(0xffffffffu, contrib, s);
                    excl_prefix += contrib;
                    break;
                } else {
                    float contrib = val;
#pragma unroll
                    for (int s = 16; s; s >>= 1)
                        contrib += __shfl_xor_sync(0xffffffffu, contrib, s);
                    excl_prefix += contrib;
                    window_hi -= 32;
                }
            }
            if (lane == 0)
                st_desc(&g_desc[bid], pack_desc(FLAG_INC, excl_prefix + block_total));
        }
        if (lane == 0) s_prefix = excl_prefix;
    }
    __syncthreads();

    const float prefix = s_prefix + thread_excl;

    // ---- fused epilogue: ev-masked (pred - log(S)) reduction ----
    float local = 0.f;
    int   cnt   = 0;
    if (full) {
        const int4* e4 = reinterpret_cast<const int4*>(yevent + base);
#pragma unroll
        for (int j = 0; j < ITEMS / 4; j++) {
            int4 ev = e4[j];
            int evs[4] = {ev.x, ev.y, ev.z, ev.w};
#pragma unroll
            for (int l = 0; l < 4; l++) {
                int k = j * 4 + l;
                float fe = (float)evs[l];
                local += fe * (p[k] - __logf(prefix + c[k]));
                cnt   += evs[l];
            }
        }
    } else {
#pragma unroll
        for (int k = 0; k < ITEMS; k++) {
            if ((base + k) < (long long)n) {
                int e = yevent[base + k];
                float fe = (float)e;
                local += fe * (p[k] - __logf(prefix + c[k]));
                cnt   += e;
            }
        }
    }

    // ---- block reduction -> global accumulators ----
#pragma unroll
    for (int s = 16; s; s >>= 1) {
        local += __shfl_down_sync(0xffffffffu, local, s);
        cnt   += __shfl_down_sync(0xffffffffu, cnt, s);
    }
    if (lane == 0) { s_loc[wid] = local; s_cnt[wid] = cnt; }
    __syncthreads();
    if (tid == 0) {
        float L = 0.f; int C = 0;
#pragma unroll
        for (int i = 0; i < BLOCK / 32; i++) { L += s_loc[i]; C += s_cnt[i]; }
        atomicAdd(&g_sum, (double)L);
        atomicAdd(&g_cnt, C);
    }
}

__global__ void nll_finalize_kernel(float* out) {
    out[0] = (float)(-(g_sum / (double)g_cnt));
}

extern "C" void kernel_launch(void* const* d_in, const int* in_sizes, int n_in,
                              void* d_out, int out_size) {
    const float* pred   = (const float*)d_in[0];
    // d_in[1] = ytime (int32) — unused by the math, deliberately not read.
    const int*   yevent = (const int*)d_in[2];
    float*       out    = (float*)d_out;

    int n = in_sizes[0];
    int nblocks = (n + TILE - 1) / TILE;   // 4096 for N=16777216

    nll_reset_kernel<<<(nblocks + 255) / 256, 256>>>(nblocks);
    nll_scan_kernel<<<nblocks, BLOCK>>>(pred, yevent, n);
    nll_finalize_kernel<<<1, 1>>>(out);
}

// round 3
// speedup vs baseline: 1.0594x; 1.0594x over previous
#include <cuda_runtime.h>
#include <cstdint>

// Cox partial-likelihood NLL, N = 16.7M time-sorted samples.
// cost = -( sum_i ev_i*(pred_i - log S_i) ) / sum_i ev_i,  S_i = cumsum exp(pred)
//
// Single-pass decoupled-lookback scan fused with the event-masked reduction.
//  * pred + yevent both loaded up front (two DRAM streams overlap the lookback)
//  * only e[k]=exp(pred) kept in regs; Sum(ev*pred) + event bitmask folded at
//    load time (lower reg pressure; log evaluated only at event positions)
//  * finalize kernel writes the scalar and resets scratch for the next replay

#define BLOCK      256
#define ITEMS      16
#define TILE       (BLOCK * ITEMS)      // 4096 elements / block
#define MAX_BLOCKS 8192                 // N=16777216 -> 4096 blocks

#define FLAG_INV 0u
#define FLAG_AGG 1u
#define FLAG_INC 2u

__device__ unsigned long long g_desc[MAX_BLOCKS];  // zero-init at module load
__device__ double             g_sum;
__device__ int                g_cnt;

__device__ __forceinline__ unsigned long long ld_desc(const unsigned long long* p) {
    unsigned long long v;
    asm volatile("ld.acquire.gpu.u64 %0, [%1];" : "=l"(v) : "l"(p) : "memory");
    return v;
}
__device__ __forceinline__ void st_desc(unsigned long long* p, unsigned long long v) {
    asm volatile("st.release.gpu.u64 [%0], %1;" :: "l"(p), "l"(v) : "memory");
}
__device__ __forceinline__ unsigned long long pack_desc(unsigned flag, float v) {
    return ((unsigned long long)flag << 32) | (unsigned long long)__float_as_uint(v);
}
__device__ __forceinline__ float    desc_val (unsigned long long d) { return __uint_as_float((unsigned)d); }
__device__ __forceinline__ unsigned desc_flag(unsigned long long d) { return (unsigned)(d >> 32); }

__global__ void __launch_bounds__(BLOCK)
nll_scan_kernel(const float* __restrict__ pred,
                const int*   __restrict__ yevent,
                int n) {
    __shared__ float s_warp[BLOCK / 32];
    __shared__ float s_prefix;
    __shared__ float s_loc[BLOCK / 32];
    __shared__ int   s_cnt[BLOCK / 32];

    const int bid  = blockIdx.x;
    const int tid  = threadIdx.x;
    const int lane = tid & 31;
    const int wid  = tid >> 5;

    const long long base = (long long)bid * TILE + (long long)tid * ITEMS;
    const bool full = (base + ITEMS) <= (long long)n;

    // ---- load BOTH streams up front (max MLP), fold ev into mask + sum ----
    float    e[ITEMS];       // exp(pred_k)
    float    sum_ev_p = 0.f; // sum of ev*pred for this thread
    unsigned mask     = 0u;  // event bitmask

    if (full) {
        const float4* p4 = reinterpret_cast<const float4*>(pred   + base);
        const int4*   v4 = reinterpret_cast<const int4*>  (yevent + base);
        float4 pv[ITEMS / 4];
        int4   ev[ITEMS / 4];
#pragma unroll
        for (int j = 0; j < ITEMS / 4; j++) pv[j] = p4[j];
#pragma unroll
        for (int j = 0; j < ITEMS / 4; j++) ev[j] = v4[j];
#pragma unroll
        for (int j = 0; j < ITEMS / 4; j++) {
            float pk[4] = {pv[j].x, pv[j].y, pv[j].z, pv[j].w};
            int   ek[4] = {ev[j].x, ev[j].y, ev[j].z, ev[j].w};
#pragma unroll
            for (int l = 0; l < 4; l++) {
                int k = j * 4 + l;
                e[k] = __expf(pk[l]);
                if (ek[l]) { sum_ev_p += pk[l]; mask |= (1u << k); }
            }
        }
    } else {
#pragma unroll
        for (int k = 0; k < ITEMS; k++) {
            bool inb = (base + k) < (long long)n;
            float pk = inb ? pred[base + k] : 0.f;
            int   ek = inb ? yevent[base + k] : 0;
            e[k] = inb ? __expf(pk) : 0.f;
            if (ek) { sum_ev_p += pk; mask |= (1u << k); }
        }
    }

    float thread_total = 0.f;
#pragma unroll
    for (int k = 0; k < ITEMS; k++) thread_total += e[k];

    // ---- block-wide exclusive scan of per-thread totals ----
    float x = thread_total;
#pragma unroll
    for (int d = 1; d < 32; d <<= 1) {
        float y = __shfl_up_sync(0xffffffffu, x, d);
        if (lane >= d) x += y;
    }
    if (lane == 31) s_warp[wid] = x;
    __syncthreads();
    if (wid == 0) {
        float w = (lane < BLOCK / 32) ? s_warp[lane] : 0.f;
#pragma unroll
        for (int d = 1; d < BLOCK / 32; d <<= 1) {
            float y = __shfl_up_sync(0xffffffffu, w, d);
            if (lane >= d) w += y;
        }
        if (lane < BLOCK / 32) s_warp[lane] = w;
    }
    __syncthreads();
    const float warp_excl   = (wid > 0) ? s_warp[wid - 1] : 0.f;
    const float thread_excl = warp_excl + (x - thread_total);
    const float block_total = s_warp[BLOCK / 32 - 1];

    // ---- decoupled lookback (warp 0) ----
    if (wid == 0) {
        if (lane == 0) {
            unsigned long long v = (bid == 0) ? pack_desc(FLAG_INC, block_total)
                                              : pack_desc(FLAG_AGG, block_total);
            st_desc(&g_desc[bid], v);
        }
        float excl_prefix = 0.f;
        if (bid > 0) {
            int window_hi = bid - 1;
            while (true) {
                int idx = window_hi - lane;
                unsigned long long d;
                unsigned f;
                do {
                    d = (idx >= 0) ? ld_desc(&g_desc[idx]) : pack_desc(FLAG_INC, 0.f);
                    f = desc_flag(d);
                } while (__any_sync(0xffffffffu, f == FLAG_INV));
                float val = desc_val(d);
                unsigned incmask = __ballot_sync(0xffffffffu, f == FLAG_INC);
                if (incmask) {
                    int first = __ffs(incmask) - 1;   // nearest INC predecessor
                    float contrib = (lane <= first) ? val : 0.f;
#pragma unroll
                    for (int s = 16; s; s >>= 1)
                        contrib += __shfl_xor_sync(0xffffffffu, contrib, s);
                    excl_prefix += contrib;
                    break;
                } else {
                    float contrib = val;
#pragma unroll
                    for (int s = 16; s; s >>= 1)
                        contrib += __shfl_xor_sync(0xffffffffu, contrib, s);
                    excl_prefix += contrib;
                    window_hi -= 32;
                }
            }
            if (lane == 0)
                st_desc(&g_desc[bid], pack_desc(FLAG_INC, excl_prefix + block_total));
        }
        if (lane == 0) s_prefix = excl_prefix;
    }
    __syncthreads();

    // ---- epilogue: Sum(ev*pred) - Sum(ev*log S) ----
    float run  = s_prefix + thread_excl;
    float logs = 0.f;
#pragma unroll
    for (int k = 0; k < ITEMS; k++) {
        run += e[k];
        if ((mask >> k) & 1u) logs += __logf(run);
    }
    float local = sum_ev_p - logs;
    int   cnt   = __popc(mask);

    // ---- block reduction -> global accumulators ----
#pragma unroll
    for (int s = 16; s; s >>= 1) {
        local += __shfl_down_sync(0xffffffffu, local, s);
        cnt   += __shfl_down_sync(0xffffffffu, cnt, s);
    }
    if (lane == 0) { s_loc[wid] = local; s_cnt[wid] = cnt; }
    __syncthreads();
    if (tid == 0) {
        float L = 0.f; int C = 0;
#pragma unroll
        for (int i = 0; i < BLOCK / 32; i++) { L += s_loc[i]; C += s_cnt[i]; }
        atomicAdd(&g_sum, (double)L);
        atomicAdd(&g_cnt, C);
    }
}

// Writes the scalar, then resets all scratch for the next graph replay.
__global__ void nll_finalize_reset_kernel(float* out, int nblocks) {
    int i = blockIdx.x * blockDim.x + threadIdx.x;
    if (i == 0) {
        out[0] = (float)(-(g_sum / (double)g_cnt));
        g_sum = 0.0;
        g_cnt = 0;
    }
    for (int j = i; j < nblocks; j += gridDim.x * blockDim.x)
        g_desc[j] = 0ull;
}

extern "C" void kernel_launch(void* const* d_in, const int* in_sizes, int n_in,
                              void* d_out, int out_size) {
    const float* pred   = (const float*)d_in[0];
    // d_in[1] = ytime — unused by the math, never read.
    const int*   yevent = (const int*)d_in[2];
    float*       out    = (float*)d_out;

    int n = in_sizes[0];
    int nblocks = (n + TILE - 1) / TILE;   // 4096

    nll_scan_kernel<<<nblocks, BLOCK>>>(pred, yevent, n);
    nll_finalize_reset_kernel<<<16, 256>>>(out, nblocks);
}

// round 6
// speedup vs baseline: 1.7164x; 1.6202x over previous
#include <cuda_runtime.h>
#include <cstdint>

// Cox partial-likelihood NLL, N = 16.7M time-sorted samples.
// cost = -( sum_i ev_i*(pred_i - log S_i) ) / sum_i ev_i,  S_i = cumsum exp(pred)
//
// Reduce-then-scan (no decoupled lookback, no inter-block spinning).
//  K1: per-block sums of exp(pred); pred kept L2-resident via a
//      createpolicy-based L2::evict_last cache-hint load (valid PTX).
//  K2: pred re-read (L2 hits) + yevent streamed (__ldcs, evict-first); each
//      block sums its predecessors' block sums directly; fused event-masked
//      log reduction.
//  K3: finalize + reset for the next graph replay.

#define BLOCK      256
#define ITEMS      16
#define TILE       (BLOCK * ITEMS)      // 4096 elements / block
#define MAX_BLOCKS 8192                 // N=16777216 -> 4096 blocks

__device__ float  g_bsum[MAX_BLOCKS];
__device__ double g_sum;
__device__ int    g_cnt;

// L2 evict_last policy load: createpolicy + ld.global.L2::cache_hint (PTX ISA-legal).
__device__ __forceinline__ unsigned long long mk_evict_last_policy() {
    unsigned long long pol;
    asm volatile("createpolicy.fractional.L2::evict_last.b64 %0, 1.0;" : "=l"(pol));
    return pol;
}
__device__ __forceinline__ float4 ld_policy(const float4* p, unsigned long long pol) {
    float4 v;
    asm volatile("ld.global.L2::cache_hint.v4.f32 {%0,%1,%2,%3}, [%4], %5;"
                 : "=f"(v.x), "=f"(v.y), "=f"(v.z), "=f"(v.w)
                 : "l"(p), "l"(pol));
    return v;
}

// ---------------- K1: per-block reduce of exp(pred) ----------------
__global__ void __launch_bounds__(BLOCK)
nll_reduce_kernel(const float* __restrict__ pred, int n) {
    __shared__ float s_warp[BLOCK / 32];

    const int bid  = blockIdx.x;
    const int tid  = threadIdx.x;
    const int lane = tid & 31;
    const int wid  = tid >> 5;

    const long long base = (long long)bid * TILE + (long long)tid * ITEMS;
    const bool full = (base + ITEMS) <= (long long)n;

    float t = 0.f;
    if (full) {
        const unsigned long long pol = mk_evict_last_policy();
        const float4* p4 = reinterpret_cast<const float4*>(pred + base);
        float4 pv[ITEMS / 4];
#pragma unroll
        for (int j = 0; j < ITEMS / 4; j++) pv[j] = ld_policy(p4 + j, pol);
#pragma unroll
        for (int j = 0; j < ITEMS / 4; j++) {
            t += __expf(pv[j].x); t += __expf(pv[j].y);
            t += __expf(pv[j].z); t += __expf(pv[j].w);
        }
    } else {
#pragma unroll
        for (int k = 0; k < ITEMS; k++)
            if ((base + k) < (long long)n) t += __expf(pred[base + k]);
    }

#pragma unroll
    for (int s = 16; s; s >>= 1) t += __shfl_xor_sync(0xffffffffu, t, s);
    if (lane == 0) s_warp[wid] = t;
    __syncthreads();
    if (tid == 0) {
        float b = 0.f;
#pragma unroll
        for (int i = 0; i < BLOCK / 32; i++) b += s_warp[i];
        g_bsum[bid] = b;
    }
}

// ---------------- K2: fused scan + event-masked log reduction ----------------
__global__ void __launch_bounds__(BLOCK)
nll_main_kernel(const float* __restrict__ pred,
                const int*   __restrict__ yevent,
                int n) {
    __shared__ float s_warp[BLOCK / 32];
    __shared__ float s_red[BLOCK / 32];
    __shared__ float s_bx;
    __shared__ float s_loc[BLOCK / 32];
    __shared__ int   s_cnt[BLOCK / 32];

    const int bid  = blockIdx.x;
    const int tid  = threadIdx.x;
    const int lane = tid & 31;
    const int wid  = tid >> 5;

    const long long base = (long long)bid * TILE + (long long)tid * ITEMS;
    const bool full = (base + ITEMS) <= (long long)n;

    // ---- start predecessor-prefix loads early (overlap with exp unpack) ----
    float bx = 0.f;
    for (int j = tid; j < bid; j += BLOCK) bx += __ldg(&g_bsum[j]);

    // ---- load both streams; pred likely L2-resident, yevent streamed ----
    float    e[ITEMS];
    float    sum_ev_p = 0.f;
    unsigned mask     = 0u;

    if (full) {
        const float4* p4 = reinterpret_cast<const float4*>(pred   + base);
        const int4*   v4 = reinterpret_cast<const int4*>  (yevent + base);
        float4 pv[ITEMS / 4];
        int4   ev[ITEMS / 4];
#pragma unroll
        for (int j = 0; j < ITEMS / 4; j++) pv[j] = __ldg(p4 + j);
#pragma unroll
        for (int j = 0; j < ITEMS / 4; j++) ev[j] = __ldcs(v4 + j);
#pragma unroll
        for (int j = 0; j < ITEMS / 4; j++) {
            float pk[4] = {pv[j].x, pv[j].y, pv[j].z, pv[j].w};
            int   ek[4] = {ev[j].x, ev[j].y, ev[j].z, ev[j].w};
#pragma unroll
            for (int l = 0; l < 4; l++) {
                int k = j * 4 + l;
                e[k] = __expf(pk[l]);
                if (ek[l]) { sum_ev_p += pk[l]; mask |= (1u << k); }
            }
        }
    } else {
#pragma unroll
        for (int k = 0; k < ITEMS; k++) {
            bool inb = (base + k) < (long long)n;
            float pk = inb ? pred[base + k] : 0.f;
            int   ek = inb ? yevent[base + k] : 0;
            e[k] = inb ? __expf(pk) : 0.f;
            if (ek) { sum_ev_p += pk; mask |= (1u << k); }
        }
    }

    // ---- reduce predecessor prefix across the block ----
#pragma unroll
    for (int s = 16; s; s >>= 1) bx += __shfl_xor_sync(0xffffffffu, bx, s);
    if (lane == 0) s_red[wid] = bx;

    // ---- block-wide exclusive scan of per-thread totals ----
    float thread_total = 0.f;
#pragma unroll
    for (int k = 0; k < ITEMS; k++) thread_total += e[k];

    float x = thread_total;
#pragma unroll
    for (int d = 1; d < 32; d <<= 1) {
        float y = __shfl_up_sync(0xffffffffu, x, d);
        if (lane >= d) x += y;
    }
    if (lane == 31) s_warp[wid] = x;
    __syncthreads();
    if (wid == 0) {
        float w = (lane < BLOCK / 32) ? s_warp[lane] : 0.f;
#pragma unroll
        for (int d = 1; d < BLOCK / 32; d <<= 1) {
            float y = __shfl_up_sync(0xffffffffu, w, d);
            if (lane >= d) w += y;
        }
        if (lane < BLOCK / 32) s_warp[lane] = w;
        if (lane == 0) {
            float b = 0.f;
#pragma unroll
            for (int i = 0; i < BLOCK / 32; i++) b += s_red[i];
            s_bx = b;
        }
    }
    __syncthreads();
    const float warp_excl   = (wid > 0) ? s_warp[wid - 1] : 0.f;
    const float thread_excl = warp_excl + (x - thread_total);

    // ---- epilogue: Sum(ev*pred) - Sum(ev*log S) ----
    float run  = s_bx + thread_excl;
    float logs = 0.f;
#pragma unroll
    for (int k = 0; k < ITEMS; k++) {
        run += e[k];
        if ((mask >> k) & 1u) logs += __logf(run);
    }
    float local = sum_ev_p - logs;
    int   cnt   = __popc(mask);

#pragma unroll
    for (int s = 16; s; s >>= 1) {
        local += __shfl_down_sync(0xffffffffu, local, s);
        cnt   += __shfl_down_sync(0xffffffffu, cnt, s);
    }
    if (lane == 0) { s_loc[wid] = local; s_cnt[wid] = cnt; }
    __syncthreads();
    if (tid == 0) {
        float L = 0.f; int C = 0;
#pragma unroll
        for (int i = 0; i < BLOCK / 32; i++) { L += s_loc[i]; C += s_cnt[i]; }
        atomicAdd(&g_sum, (double)L);
        atomicAdd(&g_cnt, C);
    }
}

// ---------------- K3: finalize + reset for next replay ----------------
__global__ void nll_finalize_reset_kernel(float* out) {
    out[0] = (float)(-(g_sum / (double)g_cnt));
    g_sum = 0.0;
    g_cnt = 0;
}

extern "C" void kernel_launch(void* const* d_in, const int* in_sizes, int n_in,
                              void* d_out, int out_size) {
    const float* pred   = (const float*)d_in[0];
    // d_in[1] = ytime — unused by the math, never read.
    const int*   yevent = (const int*)d_in[2];
    float*       out    = (float*)d_out;

    int n = in_sizes[0];
    int nblocks = (n + TILE - 1) / TILE;   // 4096

    nll_reduce_kernel<<<nblocks, BLOCK>>>(pred, n);
    nll_main_kernel<<<nblocks, BLOCK>>>(pred, yevent, n);
    nll_finalize_reset_kernel<<<1, 1>>>(out);
}